// round 8
// baseline (speedup 1.0000x reference)
#include <cuda_runtime.h>

// Problem constants
constexpr int C      = 128;            // channels
constexpr int NROW   = 32;             // rows of the similarity matrix
constexpr int P      = 1024;           // pixels per image
constexpr int PPB    = 4;              // pixels per block
constexpr int NBLK   = P / PPB;        // 256 blocks
constexpr int NSTR   = C * PPB + 4;    // 516: smem n-stride (16B-aligned rows)
constexpr int NTHR   = 320;            // 10 warps: one per upper-tri 8x8 tile
constexpr int NSLOT  = 10;
constexpr int TAILB  = 10;             // tail kernel blocks

// Scratch (no allocations allowed)
__device__ __align__(16) float g_partial[NBLK * NSLOT * 64];   // 640 KB
__device__ __align__(16) float g_dist[NSLOT * 64];
__device__ unsigned int g_counter;                              // zero-init

// Upper-triangle tile pairs (ta<=tb):
// slot: 0:(0,0) 1:(0,1) 2:(0,2) 3:(0,3) 4:(1,1) 5:(1,2) 6:(1,3) 7:(2,2) 8:(2,3) 9:(3,3)
__device__ __constant__ int c_TA[10] = {0,0,0,0,1,1,1,2,2,3};
__device__ __constant__ int c_TB[10] = {0,1,2,3,1,2,3,2,3,3};
__device__ __constant__ int c_SLOT[16] = {0,1,2,3, 1,4,5,6, 2,5,7,8, 3,6,8,9};

// ---------------------------------------------------------------------------
// Fused kernel (2 blocks/SM):
//   Phase 1 (warps 0-7): thread (n=lane, k=warp) loads its n's 16-channel
//     slice as 16 float4, computes exp in registers, accumulates s=SUM e,
//     q=SUM e^2 while storing to zs -> one smem partial per thread.
//   Phase 2 (128 threads): combine 8 partials -> rs=1/s, ai=q/s^2
//     (overlapped with other warps starting the Gram).
//   Phase 3: symmetric per-pixel Gram on raw exponentials (10 tile-warps).
//   Phase 4: 3-step reduce-scatter over cq lanes -> lane owns tile-row cq.
//   Phase 5: d2 = ai+aj-2*rs_i*rs_j*D; sqrt; pixel-sum via 2 shfl; write.
// ---------------------------------------------------------------------------
__global__ void __launch_bounds__(NTHR, 2) fused_kernel(
    const float* __restrict__ zi1, const float* __restrict__ zi2,
    const float* __restrict__ zj1, const float* __restrict__ zj2)
{
    extern __shared__ float zs[];                 // [32 n][516]
    __shared__ __align__(16) float sP[8 * 128];   // [k][n*4+pix] partial sums
    __shared__ __align__(16) float sQ[8 * 128];   // [k][n*4+pix] partial sq-sums
    __shared__ float sA[NROW * PPB];              // [n*4+pix] q/s^2
    __shared__ float sR[NROW * PPB];              // [n*4+pix] 1/s
    const int t  = threadIdx.x;
    const int p0 = blockIdx.x * PPB;

    // ---- Phase 1: load + exp + register-resident softmax partials -----------
    // Thread (n = lane, k = warp) owns channels k*16..k*16+15 of row n.
    // STS addr word = n*516 + (k*16+cc)*4: 8-lane phases hit banks 4n+{0..3}
    // exactly once -> conflict-free STS.128.
    if (t < 256) {
        const int n = t & 31;
        const int k = t >> 5;
        const float* s = (n < 16) ? (n < 8 ? zi1 : zi2)
                                  : (n < 24 ? zj1 : zj2);
        const float* sp = s + ((((n & 7) << 7) | (k << 4)) << 10) + p0;
        float4 v[16];
        #pragma unroll
        for (int cc = 0; cc < 16; cc++)
            v[cc] = *(const float4*)(sp + (cc << 10));

        float4 sv = make_float4(0.f, 0.f, 0.f, 0.f);
        float4 qv = make_float4(0.f, 0.f, 0.f, 0.f);
        float* zrow = zs + n * NSTR + (k << 6);
        #pragma unroll
        for (int cc = 0; cc < 16; cc++) {
            float4 e;
            e.x = __expf(v[cc].x); e.y = __expf(v[cc].y);
            e.z = __expf(v[cc].z); e.w = __expf(v[cc].w);
            *(float4*)(zrow + (cc << 2)) = e;
            sv.x += e.x; sv.y += e.y; sv.z += e.z; sv.w += e.w;
            qv.x = fmaf(e.x, e.x, qv.x); qv.y = fmaf(e.y, e.y, qv.y);
            qv.z = fmaf(e.z, e.z, qv.z); qv.w = fmaf(e.w, e.w, qv.w);
        }
        *(float4*)(sP + (k << 7) + (n << 2)) = sv;
        *(float4*)(sQ + (k << 7) + (n << 2)) = qv;
    }
    __syncthreads();

    // ---- Phase 2 (threads 0-127): combine the 8 channel-slice partials ------
    if (t < NROW * PPB) {
        float s = 0.f, q = 0.f;
        #pragma unroll
        for (int k = 0; k < 8; k++) {
            s += sP[(k << 7) + t];
            q += sQ[(k << 7) + t];
        }
        const float rs = __fdividef(1.f, s);
        sR[t] = rs;                  // t = n*4 + pix
        sA[t] = q * rs * rs;
    }

    // ---- Phase 3: per-pixel Gram on raw exponentials ------------------------
    // warp = tile slot; lane = cq*4 + pix; c = cc*8 + cq.
    // LDS addr = row*516 + cc*32 + lane: 32 consecutive words, conflict-free.
    const int slot = t >> 5;
    const int lane = t & 31;
    const int cq   = lane >> 2;
    const int pix  = lane & 3;
    const int ti   = c_TA[slot] * 8;
    const int tj   = c_TB[slot] * 8;

    float acc[64];
    #pragma unroll
    for (int e = 0; e < 64; e++) acc[e] = 0.f;

    #pragma unroll 4
    for (int cc = 0; cc < 16; cc++) {
        const float* zc = zs + cc * 32 + lane;
        float a[8], b[8];
        #pragma unroll
        for (int k = 0; k < 8; k++) a[k] = zc[(ti + k) * NSTR];
        #pragma unroll
        for (int l = 0; l < 8; l++) b[l] = zc[(tj + l) * NSTR];
        #pragma unroll
        for (int k = 0; k < 8; k++)
            #pragma unroll
            for (int l = 0; l < 8; l++)
                acc[k * 8 + l] = fmaf(a[k], b[l], acc[k * 8 + l]);
    }
    __syncthreads();                 // also publishes sA/sR (phase 2)

    // ---- Phase 4: reduce-scatter over cq (lane bits 4,3,2) ------------------
    {
        const bool h2 = (lane & 16) != 0;
        #pragma unroll
        for (int i = 0; i < 32; i++) {
            const float keep = h2 ? acc[i + 32] : acc[i];
            const float send = h2 ? acc[i]      : acc[i + 32];
            acc[i] = keep + __shfl_xor_sync(0xFFFFFFFFu, send, 16);
        }
        const bool h1 = (lane & 8) != 0;
        #pragma unroll
        for (int i = 0; i < 16; i++) {
            const float keep = h1 ? acc[i + 16] : acc[i];
            const float send = h1 ? acc[i]      : acc[i + 16];
            acc[i] = keep + __shfl_xor_sync(0xFFFFFFFFu, send, 8);
        }
        const bool h0 = (lane & 4) != 0;
        #pragma unroll
        for (int i = 0; i < 8; i++) {
            const float keep = h0 ? acc[i + 8] : acc[i];
            const float send = h0 ? acc[i]     : acc[i + 8];
            acc[i] = keep + __shfl_xor_sync(0xFFFFFFFFu, send, 4);
        }
    }

    // ---- Phase 5: deferred normalization, d2 -> sqrt, pixel-sum -------------
    {
        const float rsi = sR[(ti + cq) * PPB + pix];
        const float ai  = sA[(ti + cq) * PPB + pix];
        #pragma unroll
        for (int e = 0; e < 8; e++) {
            const float rsj = sR[(tj + e) * PPB + pix];
            const float aj  = sA[(tj + e) * PPB + pix];
            const float f   = rsi * rsj;
            float d2 = fmaf(-2.f * f, acc[e], ai + aj);
            d2 = fmaxf(d2, 0.f);
            asm("sqrt.approx.f32 %0, %1;" : "=f"(acc[e]) : "f"(d2));
        }
        #pragma unroll
        for (int e = 0; e < 8; e++) {
            float v = acc[e];
            v += __shfl_xor_sync(0xFFFFFFFFu, v, 1);
            v += __shfl_xor_sync(0xFFFFFFFFu, v, 2);
            acc[e] = v;
        }
        if (pix == 0) {
            float* gp = g_partial + (blockIdx.x * NSLOT + slot) * 64 + cq * 8;
            *(float4*)(gp)     = make_float4(acc[0], acc[1], acc[2], acc[3]);
            *(float4*)(gp + 4) = make_float4(acc[4], acc[5], acc[6], acc[7]);
        }
    }
}

// ---------------------------------------------------------------------------
// Tail kernel: 10 blocks reduce the 256 block-partials (float4 entries,
// 256B-coalesced); the LAST block to finish (atomic ticket, threadfence) runs
// the one-warp loss. Result is order-independent -> deterministic.
// ---------------------------------------------------------------------------
__global__ __launch_bounds__(256) void tail_kernel(float* __restrict__ out)
{
    __shared__ __align__(16) float4 smf[16 * 16];  // [part][f4]
    __shared__ unsigned int sticket;
    const int t    = threadIdx.x;
    const int f4   = t & 15;
    const int part = t >> 4;
    const float4* src = (const float4*)g_partial + blockIdx.x * 16 + f4;

    float4 a0 = make_float4(0.f,0.f,0.f,0.f), a1 = a0, a2 = a0, a3 = a0;
    #pragma unroll
    for (int i = 0; i < 16; i += 4) {
        const float4 v0 = src[(part * 16 + i + 0) * 160];
        const float4 v1 = src[(part * 16 + i + 1) * 160];
        const float4 v2 = src[(part * 16 + i + 2) * 160];
        const float4 v3 = src[(part * 16 + i + 3) * 160];
        a0.x += v0.x; a0.y += v0.y; a0.z += v0.z; a0.w += v0.w;
        a1.x += v1.x; a1.y += v1.y; a1.z += v1.z; a1.w += v1.w;
        a2.x += v2.x; a2.y += v2.y; a2.z += v2.z; a2.w += v2.w;
        a3.x += v3.x; a3.y += v3.y; a3.z += v3.z; a3.w += v3.w;
    }
    float4 r;
    r.x = (a0.x + a1.x) + (a2.x + a3.x);
    r.y = (a0.y + a1.y) + (a2.y + a3.y);
    r.z = (a0.z + a1.z) + (a2.z + a3.z);
    r.w = (a0.w + a1.w) + (a2.w + a3.w);
    smf[part * 16 + f4] = r;
    __syncthreads();

    if (t < 16) {
        float4 s = make_float4(0.f, 0.f, 0.f, 0.f);
        #pragma unroll
        for (int p = 0; p < 16; p++) {
            const float4 v = smf[p * 16 + t];
            s.x += v.x; s.y += v.y; s.z += v.z; s.w += v.w;
        }
        const float sc = 1.f / 1024.f;
        s.x *= sc; s.y *= sc; s.z *= sc; s.w *= sc;
        ((float4*)g_dist)[blockIdx.x * 16 + t] = s;
        __threadfence();                         // release g_dist writes
    }
    __syncthreads();
    if (t == 0) sticket = atomicAdd(&g_counter, 1);
    __syncthreads();

    if (sticket == TAILB - 1) {                  // last block: all g_dist done
        if (t == 0) g_counter = 0;               // reset for next graph replay
        __threadfence();
        if (t < 32) {
            const int r2 = t;
            const int ra = r2 >> 3;
            float row[32];
            #pragma unroll
            for (int j = 0; j < 32; j++) {
                const int b = j >> 3;
                const int s = c_SLOT[ra * 4 + b];
                const int e = (ra <= b) ? ((r2 & 7) * 8 + (j & 7))
                                        : ((j & 7) * 8 + (r2 & 7));
                row[j] = __expf(-g_dist[s * 64 + e]);
            }
            const int pr = r2 ^ 16;              // positive partner (K=16)
            const float pos = row[pr];
            float m = pos;
            #pragma unroll
            for (int j = 0; j < 32; j++)
                if (j != r2 && j != pr) m = fmaxf(m, row[j]);
            float s = __expf(pos - m);
            #pragma unroll
            for (int j = 0; j < 32; j++)
                if (j != r2 && j != pr) s += __expf(row[j] - m);
            float rl = __logf(s) + m - pos;      // logsumexp - logits[:,0]

            #pragma unroll
            for (int off = 16; off > 0; off >>= 1)
                rl += __shfl_down_sync(0xFFFFFFFFu, rl, off);

            if (r2 == 0) out[0] = rl * (1.f / 32.f);
        }
    }
}

// ---------------------------------------------------------------------------
extern "C" void kernel_launch(void* const* d_in, const int* in_sizes, int n_in,
                              void* d_out, int out_size)
{
    (void)in_sizes; (void)n_in; (void)out_size;
    const float* zi1 = (const float*)d_in[0];
    const float* zi2 = (const float*)d_in[1];
    const float* zj1 = (const float*)d_in[2];
    const float* zj2 = (const float*)d_in[3];
    float* out = (float*)d_out;

    const int smem = NROW * NSTR * (int)sizeof(float);   // 66048 B dynamic
    cudaFuncSetAttribute(fused_kernel,
                         cudaFuncAttributeMaxDynamicSharedMemorySize, smem);

    fused_kernel<<<NBLK, NTHR, smem>>>(zi1, zi2, zj1, zj2);
    tail_kernel<<<TAILB, 256>>>(out);
}

// round 9
// speedup vs baseline: 1.0014x; 1.0014x over previous
#include <cuda_runtime.h>

// Problem constants
constexpr int C      = 128;            // channels
constexpr int NROW   = 32;             // rows of the similarity matrix
constexpr int P      = 1024;           // pixels per image
constexpr int PPB    = 4;              // pixels per block
constexpr int NBLK   = P / PPB;        // 256 blocks
constexpr int NSTR   = C * PPB + 4;    // 516: smem n-stride (16B-aligned rows)
constexpr int NTHR   = 320;            // 10 warps: one per upper-tri 8x8 tile
constexpr int NSLOT  = 10;

// Scratch (no allocations allowed)
__device__ __align__(16) float g_partial[NBLK * NSLOT * 64];   // 640 KB
__device__ __align__(16) float g_dist[NSLOT * 64];

// Upper-triangle tile pairs (ta<=tb):
// slot: 0:(0,0) 1:(0,1) 2:(0,2) 3:(0,3) 4:(1,1) 5:(1,2) 6:(1,3) 7:(2,2) 8:(2,3) 9:(3,3)
__device__ __constant__ int c_TA[10] = {0,0,0,0,1,1,1,2,2,3};
__device__ __constant__ int c_TB[10] = {0,1,2,3,1,2,3,2,3,3};
__device__ __constant__ int c_SLOT[16] = {0,1,2,3, 1,4,5,6, 2,5,7,8, 3,6,8,9};

// ---------------------------------------------------------------------------
// Fused kernel (2 blocks/SM):
//   Phase 1 (warps 0-7): thread (n=lane, k=warp) loads its n's 16-channel
//     slice as 16 float4, computes exp in registers, accumulates s=SUM e,
//     q=SUM e^2 while storing to zs -> one smem partial per thread.
//   Phase 2 (128 threads): combine 8 partials -> rs=1/s, ai=q/s^2
//     (overlapped with other warps starting the Gram).
//   Phase 3: symmetric per-pixel Gram on raw exponentials (10 tile-warps).
//   Phase 4: 3-step reduce-scatter over cq lanes -> lane owns tile-row cq.
//   Phase 5: d2 = ai+aj-2*rs_i*rs_j*D; sqrt; pixel-sum via 2 shfl; write.
// ---------------------------------------------------------------------------
__global__ void __launch_bounds__(NTHR, 2) fused_kernel(
    const float* __restrict__ zi1, const float* __restrict__ zi2,
    const float* __restrict__ zj1, const float* __restrict__ zj2)
{
    extern __shared__ float zs[];                 // [32 n][516]
    __shared__ __align__(16) float sP[8 * 128];   // [k][n*4+pix] partial sums
    __shared__ __align__(16) float sQ[8 * 128];   // [k][n*4+pix] partial sq-sums
    __shared__ float sA[NROW * PPB];              // [n*4+pix] q/s^2
    __shared__ float sR[NROW * PPB];              // [n*4+pix] 1/s
    const int t  = threadIdx.x;
    const int p0 = blockIdx.x * PPB;

    // ---- Phase 1: load + exp + register-resident softmax partials -----------
    if (t < 256) {
        const int n = t & 31;
        const int k = t >> 5;
        const float* s = (n < 16) ? (n < 8 ? zi1 : zi2)
                                  : (n < 24 ? zj1 : zj2);
        const float* sp = s + ((((n & 7) << 7) | (k << 4)) << 10) + p0;
        float4 v[16];
        #pragma unroll
        for (int cc = 0; cc < 16; cc++)
            v[cc] = *(const float4*)(sp + (cc << 10));

        float4 sv = make_float4(0.f, 0.f, 0.f, 0.f);
        float4 qv = make_float4(0.f, 0.f, 0.f, 0.f);
        float* zrow = zs + n * NSTR + (k << 6);
        #pragma unroll
        for (int cc = 0; cc < 16; cc++) {
            float4 e;
            e.x = __expf(v[cc].x); e.y = __expf(v[cc].y);
            e.z = __expf(v[cc].z); e.w = __expf(v[cc].w);
            *(float4*)(zrow + (cc << 2)) = e;
            sv.x += e.x; sv.y += e.y; sv.z += e.z; sv.w += e.w;
            qv.x = fmaf(e.x, e.x, qv.x); qv.y = fmaf(e.y, e.y, qv.y);
            qv.z = fmaf(e.z, e.z, qv.z); qv.w = fmaf(e.w, e.w, qv.w);
        }
        *(float4*)(sP + (k << 7) + (n << 2)) = sv;
        *(float4*)(sQ + (k << 7) + (n << 2)) = qv;
    }
    __syncthreads();

    // ---- Phase 2 (threads 0-127): combine the 8 channel-slice partials ------
    if (t < NROW * PPB) {
        float s = 0.f, q = 0.f;
        #pragma unroll
        for (int k = 0; k < 8; k++) {
            s += sP[(k << 7) + t];
            q += sQ[(k << 7) + t];
        }
        const float rs = __fdividef(1.f, s);
        sR[t] = rs;                  // t = n*4 + pix
        sA[t] = q * rs * rs;
    }

    // ---- Phase 3: per-pixel Gram on raw exponentials ------------------------
    const int slot = t >> 5;
    const int lane = t & 31;
    const int cq   = lane >> 2;
    const int pix  = lane & 3;
    const int ti   = c_TA[slot] * 8;
    const int tj   = c_TB[slot] * 8;

    float acc[64];
    #pragma unroll
    for (int e = 0; e < 64; e++) acc[e] = 0.f;

    #pragma unroll 4
    for (int cc = 0; cc < 16; cc++) {
        const float* zc = zs + cc * 32 + lane;
        float a[8], b[8];
        #pragma unroll
        for (int k = 0; k < 8; k++) a[k] = zc[(ti + k) * NSTR];
        #pragma unroll
        for (int l = 0; l < 8; l++) b[l] = zc[(tj + l) * NSTR];
        #pragma unroll
        for (int k = 0; k < 8; k++)
            #pragma unroll
            for (int l = 0; l < 8; l++)
                acc[k * 8 + l] = fmaf(a[k], b[l], acc[k * 8 + l]);
    }
    __syncthreads();                 // also publishes sA/sR (phase 2)

    // ---- Phase 4: reduce-scatter over cq (lane bits 4,3,2) ------------------
    {
        const bool h2 = (lane & 16) != 0;
        #pragma unroll
        for (int i = 0; i < 32; i++) {
            const float keep = h2 ? acc[i + 32] : acc[i];
            const float send = h2 ? acc[i]      : acc[i + 32];
            acc[i] = keep + __shfl_xor_sync(0xFFFFFFFFu, send, 16);
        }
        const bool h1 = (lane & 8) != 0;
        #pragma unroll
        for (int i = 0; i < 16; i++) {
            const float keep = h1 ? acc[i + 16] : acc[i];
            const float send = h1 ? acc[i]      : acc[i + 16];
            acc[i] = keep + __shfl_xor_sync(0xFFFFFFFFu, send, 8);
        }
        const bool h0 = (lane & 4) != 0;
        #pragma unroll
        for (int i = 0; i < 8; i++) {
            const float keep = h0 ? acc[i + 8] : acc[i];
            const float send = h0 ? acc[i]     : acc[i + 8];
            acc[i] = keep + __shfl_xor_sync(0xFFFFFFFFu, send, 4);
        }
    }

    // ---- Phase 5: deferred normalization, d2 -> sqrt, pixel-sum -------------
    {
        const float rsi = sR[(ti + cq) * PPB + pix];
        const float ai  = sA[(ti + cq) * PPB + pix];
        #pragma unroll
        for (int e = 0; e < 8; e++) {
            const float rsj = sR[(tj + e) * PPB + pix];
            const float aj  = sA[(tj + e) * PPB + pix];
            const float f   = rsi * rsj;
            float d2 = fmaf(-2.f * f, acc[e], ai + aj);
            d2 = fmaxf(d2, 0.f);
            asm("sqrt.approx.f32 %0, %1;" : "=f"(acc[e]) : "f"(d2));
        }
        #pragma unroll
        for (int e = 0; e < 8; e++) {
            float v = acc[e];
            v += __shfl_xor_sync(0xFFFFFFFFu, v, 1);
            v += __shfl_xor_sync(0xFFFFFFFFu, v, 2);
            acc[e] = v;
        }
        if (pix == 0) {
            float* gp = g_partial + (blockIdx.x * NSLOT + slot) * 64 + cq * 8;
            *(float4*)(gp)     = make_float4(acc[0], acc[1], acc[2], acc[3]);
            *(float4*)(gp + 4) = make_float4(acc[4], acc[5], acc[6], acc[7]);
        }
    }
}

// ---------------------------------------------------------------------------
// Stage 2 (round-6 proven): reduce 256 block-partials into g_dist.
// Grid 40 x 256: block owns 16 entries; thread (part,eloc) sums 16
// block-partials (coalesced across eloc); 16 parts combined via smem.
// ---------------------------------------------------------------------------
__global__ __launch_bounds__(256) void sim_reduce()
{
    __shared__ float sm[16 * 17];
    const int eloc = threadIdx.x & 15;
    const int part = threadIdx.x >> 4;
    const int e    = blockIdx.x * 16 + eloc;
    const float* src = g_partial + e;

    float a0 = 0.f, a1 = 0.f, a2 = 0.f, a3 = 0.f;
    #pragma unroll
    for (int b = 0; b < 16; b += 4) {
        const int bb = part * 16 + b;
        a0 += src[(bb + 0) * (NSLOT * 64)];
        a1 += src[(bb + 1) * (NSLOT * 64)];
        a2 += src[(bb + 2) * (NSLOT * 64)];
        a3 += src[(bb + 3) * (NSLOT * 64)];
    }
    sm[part * 17 + eloc] = (a0 + a1) + (a2 + a3);
    __syncthreads();

    if (threadIdx.x < 16) {
        float s = 0.f;
        #pragma unroll
        for (int q = 0; q < 16; q++) s += sm[q * 17 + threadIdx.x];
        g_dist[blockIdx.x * 16 + threadIdx.x] = s * (1.f / 1024.f);
    }
}

// ---------------------------------------------------------------------------
// Stage 3: one warp. Lane r: gather its row's 32 distances via the slot LUT,
// sim = exp(-dist), logsumexp - positive logit, shfl tree reduce.
// ---------------------------------------------------------------------------
__global__ __launch_bounds__(32) void loss_final(float* __restrict__ out)
{
    const int r = threadIdx.x;
    const int ra = r >> 3;

    float row[32];
    #pragma unroll
    for (int j = 0; j < 32; j++) {
        const int b = j >> 3;
        const int s = c_SLOT[ra * 4 + b];
        const int e = (ra <= b) ? ((r & 7) * 8 + (j & 7))
                                : ((j & 7) * 8 + (r & 7));
        row[j] = __expf(-g_dist[s * 64 + e]);
    }

    const int pr = r ^ 16;                   // positive partner (K=16)
    const float pos = row[pr];
    float m = pos;
    #pragma unroll
    for (int j = 0; j < 32; j++)
        if (j != r && j != pr) m = fmaxf(m, row[j]);
    float s = __expf(pos - m);
    #pragma unroll
    for (int j = 0; j < 32; j++)
        if (j != r && j != pr) s += __expf(row[j] - m);
    float rl = __logf(s) + m - pos;          // logsumexp - logits[:,0]

    #pragma unroll
    for (int off = 16; off > 0; off >>= 1)
        rl += __shfl_down_sync(0xFFFFFFFFu, rl, off);

    if (r == 0) out[0] = rl * (1.f / 32.f);
}

// ---------------------------------------------------------------------------
extern "C" void kernel_launch(void* const* d_in, const int* in_sizes, int n_in,
                              void* d_out, int out_size)
{
    (void)in_sizes; (void)n_in; (void)out_size;
    const float* zi1 = (const float*)d_in[0];
    const float* zi2 = (const float*)d_in[1];
    const float* zj1 = (const float*)d_in[2];
    const float* zj2 = (const float*)d_in[3];
    float* out = (float*)d_out;

    const int smem = NROW * NSTR * (int)sizeof(float);   // 66048 B dynamic
    cudaFuncSetAttribute(fused_kernel,
                         cudaFuncAttributeMaxDynamicSharedMemorySize, smem);

    fused_kernel<<<NBLK, NTHR, smem>>>(zi1, zi2, zj1, zj2);
    sim_reduce<<<40, 256>>>();
    loss_final<<<1, 32>>>(out);
}

// round 10
// speedup vs baseline: 1.1031x; 1.1016x over previous
#include <cuda_runtime.h>

// Problem constants
constexpr int C      = 128;            // channels
constexpr int NROW   = 32;             // rows of the similarity matrix
constexpr int P      = 1024;           // pixels per image
constexpr int PPB    = 8;              // pixels per block
constexpr int NBLK   = P / PPB;        // 128 blocks
constexpr int NSTRW  = C * PPB + 8;    // 1032 words per n-row (stride % 32 == 8)
constexpr int NTHR   = 640;            // 20 warps: 10 slots x 2 j-halves
constexpr int NSLOT  = 10;

// Scratch (no allocations allowed)
__device__ __align__(16) float g_partial[NBLK * NSLOT * 64];   // 320 KB
__device__ __align__(16) float g_dist[NSLOT * 64];

// Upper-triangle tile pairs (ta<=tb):
// slot: 0:(0,0) 1:(0,1) 2:(0,2) 3:(0,3) 4:(1,1) 5:(1,2) 6:(1,3) 7:(2,2) 8:(2,3) 9:(3,3)
__device__ __constant__ int c_TA[10] = {0,0,0,0,1,1,1,2,2,3};
__device__ __constant__ int c_TB[10] = {0,1,2,3,1,2,3,2,3,3};
__device__ __constant__ int c_SLOT[16] = {0,1,2,3, 1,4,5,6, 2,5,7,8, 3,6,8,9};

#define FFMA2(acc, a, b) \
    asm("fma.rn.f32x2 %0, %1, %2, %0;" : "+l"(acc) : "l"(a), "l"(b))
#define ADDX2(d, a, b) \
    asm("add.rn.f32x2 %0, %1, %2;" : "=l"(d) : "l"(a), "l"(b))
#define LDS64(d, addr) \
    asm volatile("ld.shared.b64 %0, [%1];" : "=l"(d) : "r"(addr))

// ---------------------------------------------------------------------------
// Fused kernel (1 block/SM, 8 pixels/block):
//   Phase 1: all 640 threads load 13 float4 (lane-consecutive (c,half):
//     16 lines/warp-instr, each 32B sector read once), exp in regs, STS.128
//     into zs[n][c][pix8] (conflict-free).
//   Phase 2 (warps 0-7): per-(n,pix) softmax sums s,q via stride-8 scans
//     -> rs=1/s, ai=q/s^2, overlapped with warps 8-19 starting the Gram.
//   Phase 3: packed Gram. Warp = (slot, j-half); lane = (cq 0..7, pp 0..3);
//     c = cc*8+cq. a2[8]/b2[4] are ld.shared.b64 pixel-pairs; 32 f32x2 accs.
//   Phase 4: 3-step reduce-scatter over cq -> lane owns (i=ti+cq, 4 j's).
//   Phase 5: d2 = ai+aj-2*rs_i*rs_j*dot per pixel; sqrt; pair-sum + 2 shfl
//     over pp -> 8-pixel sums; lane pp==0 writes float4.
// ---------------------------------------------------------------------------
__global__ void __launch_bounds__(NTHR, 1) fused_kernel(
    const float* __restrict__ zi1, const float* __restrict__ zi2,
    const float* __restrict__ zj1, const float* __restrict__ zj2)
{
    extern __shared__ float zs[];            // [32 n][1032 w]
    __shared__ float sA[NROW * PPB];         // [n*8+pix] q/s^2
    __shared__ float sR[NROW * PPB];         // [n*8+pix] 1/s
    const int t  = threadIdx.x;
    const int p0 = blockIdx.x * PPB;

    // ---- Phase 1: load (16 lines/instr) + exp + STS.128 ---------------------
    {
        float4 v[13];
        #pragma unroll
        for (int q = 0; q < 13; q++) {
            const int g = t + q * NTHR;      // float4 index, 0..8191 valid
            if (g < 8192) {
                const int n = g >> 8;
                const int rem = g & 255;
                const int c = rem >> 1;
                const int h = rem & 1;
                const float* s = (n < 16) ? (n < 8 ? zi1 : zi2)
                                          : (n < 24 ? zj1 : zj2);
                v[q] = *(const float4*)(s + (((n & 7) * C + c) << 10) + p0 + h * 4);
            }
        }
        #pragma unroll
        for (int q = 0; q < 13; q++) {
            const int g = t + q * NTHR;
            if (g < 8192) {
                const int n = g >> 8;
                const int rem = g & 255;
                const int c = rem >> 1;
                const int h = rem & 1;
                float4 e;
                e.x = __expf(v[q].x); e.y = __expf(v[q].y);
                e.z = __expf(v[q].z); e.w = __expf(v[q].w);
                *(float4*)(zs + n * NSTRW + c * 8 + h * 4) = e;
            }
        }
    }
    __syncthreads();

    // ---- Phase 2 (threads 0-255): softmax sums per (n,pix) ------------------
    // Bank word = 8n + pix + 8c (stride 1032 % 32 == 8): warp = 4n x 8pix
    // covers all 32 banks exactly once -> conflict-free stride-8 scan.
    if (t < NROW * PPB) {
        const int n   = t >> 3;
        const int pix = t & 7;
        const float* col = zs + n * NSTRW + pix;
        float s0 = 0.f, s1 = 0.f, q0 = 0.f, q1 = 0.f;
        #pragma unroll 8
        for (int c = 0; c < C; c += 2) {
            const float va = col[c * 8];
            const float vb = col[(c + 1) * 8];
            s0 += va; q0 = fmaf(va, va, q0);
            s1 += vb; q1 = fmaf(vb, vb, q1);
        }
        const float rs = __fdividef(1.f, s0 + s1);
        sR[t] = rs;                          // t == n*8 + pix
        sA[t] = (q0 + q1) * rs * rs;
    }

    // ---- Phase 3: packed per-pixel-pair Gram --------------------------------
    const int w    = t >> 5;
    const int lane = t & 31;
    const int cq   = lane >> 2;
    const int pp   = lane & 3;               // pixel pair: pixels 2pp, 2pp+1
    const int slot = w >> 1;
    const int jh   = w & 1;
    const int ti   = c_TA[slot] * 8;
    const int tj   = c_TB[slot] * 8 + jh * 4;

    unsigned int zb;
    asm("{ .reg .u64 tt; cvta.to.shared.u64 tt, %1; cvt.u32.u64 %0, tt; }"
        : "=r"(zb) : "l"(zs));
    const unsigned int abase = zb + (unsigned)(ti * NSTRW + cq * 8 + pp * 2) * 4u;
    const unsigned int bbase = zb + (unsigned)(tj * NSTRW + cq * 8 + pp * 2) * 4u;

    unsigned long long acc2[32];
    #pragma unroll
    for (int e = 0; e < 32; e++) acc2[e] = 0ull;

    #pragma unroll 1
    for (int cc = 0; cc < 16; cc++) {
        // c = cc*8 + cq -> byte offset cc*256 within the row
        unsigned long long a2[8], b2[4];
        const unsigned int ao = abase + cc * 256u;
        const unsigned int bo = bbase + cc * 256u;
        #pragma unroll
        for (int k = 0; k < 8; k++) LDS64(a2[k], ao + k * (NSTRW * 4));
        #pragma unroll
        for (int l = 0; l < 4; l++) LDS64(b2[l], bo + l * (NSTRW * 4));
        #pragma unroll
        for (int k = 0; k < 8; k++)
            #pragma unroll
            for (int l = 0; l < 4; l++)
                FFMA2(acc2[k * 4 + l], a2[k], b2[l]);
    }
    __syncthreads();                         // publishes sA/sR (phase 2)

    // ---- Phase 4: reduce-scatter over cq (lane bits 4,3,2) ------------------
    // Entries e = k*4 + l; after 3 steps lane cq owns k == cq (4 entries).
    {
        const bool h2 = (lane & 16) != 0;
        #pragma unroll
        for (int i = 0; i < 16; i++) {
            const unsigned long long keep = h2 ? acc2[i + 16] : acc2[i];
            const unsigned long long send = h2 ? acc2[i]      : acc2[i + 16];
            const unsigned long long r = __shfl_xor_sync(0xFFFFFFFFu, send, 16);
            ADDX2(acc2[i], keep, r);
        }
        const bool h1 = (lane & 8) != 0;
        #pragma unroll
        for (int i = 0; i < 8; i++) {
            const unsigned long long keep = h1 ? acc2[i + 8] : acc2[i];
            const unsigned long long send = h1 ? acc2[i]     : acc2[i + 8];
            const unsigned long long r = __shfl_xor_sync(0xFFFFFFFFu, send, 8);
            ADDX2(acc2[i], keep, r);
        }
        const bool h0 = (lane & 4) != 0;
        #pragma unroll
        for (int i = 0; i < 4; i++) {
            const unsigned long long keep = h0 ? acc2[i + 4] : acc2[i];
            const unsigned long long send = h0 ? acc2[i]     : acc2[i + 4];
            const unsigned long long r = __shfl_xor_sync(0xFFFFFFFFu, send, 4);
            ADDX2(acc2[i], keep, r);
        }
    }

    // ---- Phase 5: normalize, d2 -> sqrt, pixel sums -------------------------
    {
        const float2 rsi = *(const float2*)(sR + (ti + cq) * PPB + pp * 2);
        const float2 ai  = *(const float2*)(sA + (ti + cq) * PPB + pp * 2);
        float vsum[4];
        #pragma unroll
        for (int l = 0; l < 4; l++) {
            const float2 rsj = *(const float2*)(sR + (tj + l) * PPB + pp * 2);
            const float2 aj  = *(const float2*)(sA + (tj + l) * PPB + pp * 2);
            float dx, dy;
            asm("mov.b64 {%0, %1}, %2;" : "=f"(dx), "=f"(dy) : "l"(acc2[l]));
            float d2x = fmaf(-2.f * (rsi.x * rsj.x), dx, ai.x + aj.x);
            float d2y = fmaf(-2.f * (rsi.y * rsj.y), dy, ai.y + aj.y);
            d2x = fmaxf(d2x, 0.f);
            d2y = fmaxf(d2y, 0.f);
            float sx, sy;
            asm("sqrt.approx.f32 %0, %1;" : "=f"(sx) : "f"(d2x));
            asm("sqrt.approx.f32 %0, %1;" : "=f"(sy) : "f"(d2y));
            vsum[l] = sx + sy;
        }
        #pragma unroll
        for (int l = 0; l < 4; l++) {
            float v = vsum[l];
            v += __shfl_xor_sync(0xFFFFFFFFu, v, 1);
            v += __shfl_xor_sync(0xFFFFFFFFu, v, 2);
            vsum[l] = v;                     // sum over all 8 pixels
        }
        if (pp == 0) {
            float* gp = g_partial + blockIdx.x * (NSLOT * 64)
                      + slot * 64 + cq * 8 + jh * 4;
            *(float4*)gp = make_float4(vsum[0], vsum[1], vsum[2], vsum[3]);
        }
    }
}

// ---------------------------------------------------------------------------
// Stage 2: reduce 128 block-partials into g_dist. Grid 40 x 256:
// block owns 16 entries; thread (part,eloc) sums 8 block-partials
// (coalesced across eloc); 16 parts combined via smem in fixed order.
// ---------------------------------------------------------------------------
__global__ __launch_bounds__(256) void sim_reduce()
{
    __shared__ float sm[16 * 17];
    const int eloc = threadIdx.x & 15;
    const int part = threadIdx.x >> 4;
    const int e    = blockIdx.x * 16 + eloc;
    const float* src = g_partial + e;

    float a0 = 0.f, a1 = 0.f, a2 = 0.f, a3 = 0.f;
    {
        const int bb = part * 8;
        a0 += src[(bb + 0) * (NSLOT * 64)];
        a1 += src[(bb + 1) * (NSLOT * 64)];
        a2 += src[(bb + 2) * (NSLOT * 64)];
        a3 += src[(bb + 3) * (NSLOT * 64)];
        a0 += src[(bb + 4) * (NSLOT * 64)];
        a1 += src[(bb + 5) * (NSLOT * 64)];
        a2 += src[(bb + 6) * (NSLOT * 64)];
        a3 += src[(bb + 7) * (NSLOT * 64)];
    }
    sm[part * 17 + eloc] = (a0 + a1) + (a2 + a3);
    __syncthreads();

    if (threadIdx.x < 16) {
        float s = 0.f;
        #pragma unroll
        for (int q = 0; q < 16; q++) s += sm[q * 17 + threadIdx.x];
        g_dist[blockIdx.x * 16 + threadIdx.x] = s * (1.f / 1024.f);
    }
}

// ---------------------------------------------------------------------------
// Stage 3: one warp. Lane r: gather its row's 32 distances via the slot LUT,
// sim = exp(-dist), logsumexp - positive logit, shfl tree reduce.
// ---------------------------------------------------------------------------
__global__ __launch_bounds__(32) void loss_final(float* __restrict__ out)
{
    const int r = threadIdx.x;
    const int ra = r >> 3;

    float row[32];
    #pragma unroll
    for (int j = 0; j < 32; j++) {
        const int b = j >> 3;
        const int s = c_SLOT[ra * 4 + b];
        const int e = (ra <= b) ? ((r & 7) * 8 + (j & 7))
                                : ((j & 7) * 8 + (r & 7));
        row[j] = __expf(-g_dist[s * 64 + e]);
    }

    const int pr = r ^ 16;                   // positive partner (K=16)
    const float pos = row[pr];
    float m = pos;
    #pragma unroll
    for (int j = 0; j < 32; j++)
        if (j != r && j != pr) m = fmaxf(m, row[j]);
    float s = __expf(pos - m);
    #pragma unroll
    for (int j = 0; j < 32; j++)
        if (j != r && j != pr) s += __expf(row[j] - m);
    float rl = __logf(s) + m - pos;          // logsumexp - logits[:,0]

    #pragma unroll
    for (int off = 16; off > 0; off >>= 1)
        rl += __shfl_down_sync(0xFFFFFFFFu, rl, off);

    if (r == 0) out[0] = rl * (1.f / 32.f);
}

// ---------------------------------------------------------------------------
extern "C" void kernel_launch(void* const* d_in, const int* in_sizes, int n_in,
                              void* d_out, int out_size)
{
    (void)in_sizes; (void)n_in; (void)out_size;
    const float* zi1 = (const float*)d_in[0];
    const float* zi2 = (const float*)d_in[1];
    const float* zj1 = (const float*)d_in[2];
    const float* zj2 = (const float*)d_in[3];
    float* out = (float*)d_out;

    const int smem = NROW * NSTRW * (int)sizeof(float);  // 132096 B dynamic
    cudaFuncSetAttribute(fused_kernel,
                         cudaFuncAttributeMaxDynamicSharedMemorySize, smem);

    fused_kernel<<<NBLK, NTHR, smem>>>(zi1, zi2, zj1, zj2);
    sim_reduce<<<40, 256>>>();
    loss_final<<<1, 32>>>(out);
}